// round 1
// baseline (speedup 1.0000x reference)
#include <cuda_runtime.h>
#include <math.h>

#define N_NODES 10000
#define N_EDGES 160000
#define H       128
#define F3H     384
#define E_RBF   20
#define L_LAYERS 3
#define PI_F    3.14159265358979f
#define CUTOFF_F 5.0f

#define NPB 4     // nodes per block (node kernels)
#define EPB 16    // edges per block (edge kernel)

// ---------- persistent scratch (device globals: no allocation allowed) ----------
__device__ float g_ns  [N_NODES * H];        // node_scalar
__device__ float g_vecA[N_NODES * 3 * H];    // node_vector ping
__device__ float g_vecB[N_NODES * 3 * H];    // node_vector pong
__device__ float g_so  [N_NODES * F3H];      // scalar_out (message MLP output)

__device__ __forceinline__ float silu_f(float x) {
    return x / (1.0f + expf(-x));
}

// ---------- init: node_scalar = embed[z], vecA = 0 ----------
__global__ void __launch_bounds__(H) k_init(const int* __restrict__ z,
                                            const float* __restrict__ embed) {
    int i = blockIdx.x, j = threadIdx.x;
    g_ns[i * H + j] = embed[z[i] * H + j];
#pragma unroll
    for (int d = 0; d < 3; d++) g_vecA[i * 3 * H + d * H + j] = 0.0f;
}

// ---------- vecB = vecA ----------
__global__ void k_copy_vec() {
    int idx = blockIdx.x * blockDim.x + threadIdx.x;
    const float4* src = reinterpret_cast<const float4*>(g_vecA);
    float4* dst = reinterpret_cast<float4*>(g_vecB);
    if (idx < N_NODES * 3 * H / 4) dst[idx] = src[idx];
}

// ---------- scalar_out = silu(ns @ W1 + b1) @ W2 + b2  (per node, NPB nodes/block) ----------
__global__ void __launch_bounds__(H) k_scalar_out(const float* __restrict__ W1,
                                                  const float* __restrict__ b1,
                                                  const float* __restrict__ W2,
                                                  const float* __restrict__ b2) {
    int i0 = blockIdx.x * NPB, j = threadIdx.x;
    __shared__ float s_x[NPB][H];
    __shared__ float s_h[NPB][H];
#pragma unroll
    for (int n = 0; n < NPB; n++) s_x[n][j] = g_ns[(i0 + n) * H + j];
    __syncthreads();

    float acc[NPB];
    float bb = b1[j];
#pragma unroll
    for (int n = 0; n < NPB; n++) acc[n] = bb;
    for (int k = 0; k < H; k++) {
        float w = W1[k * H + j];
#pragma unroll
        for (int n = 0; n < NPB; n++) acc[n] += s_x[n][k] * w;
    }
#pragma unroll
    for (int n = 0; n < NPB; n++) s_h[n][j] = silu_f(acc[n]);
    __syncthreads();

    float a0[NPB], a1[NPB], a2[NPB];
    float c0 = b2[j], c1 = b2[H + j], c2 = b2[2 * H + j];
#pragma unroll
    for (int n = 0; n < NPB; n++) { a0[n] = c0; a1[n] = c1; a2[n] = c2; }
    for (int k = 0; k < H; k++) {
        float w0 = W2[k * F3H + j];
        float w1 = W2[k * F3H + H + j];
        float w2 = W2[k * F3H + 2 * H + j];
#pragma unroll
        for (int n = 0; n < NPB; n++) {
            float h = s_h[n][k];
            a0[n] += h * w0; a1[n] += h * w1; a2[n] += h * w2;
        }
    }
#pragma unroll
    for (int n = 0; n < NPB; n++) {
        g_so[(i0 + n) * F3H + j]         = a0[n];
        g_so[(i0 + n) * F3H + H + j]     = a1[n];
        g_so[(i0 + n) * F3H + 2 * H + j] = a2[n];
    }
}

// ---------- edge kernel: filter, gate, scatter-add messages ----------
__global__ void __launch_bounds__(H) k_edge(const int* __restrict__ edge,
                                            const float* __restrict__ ediff,
                                            const float* __restrict__ edist,
                                            const float* __restrict__ Fw,
                                            const float* __restrict__ Fb) {
    int j = threadIdx.x;
    int e0 = blockIdx.x * EPB;

    __shared__ float s_Fw[E_RBF * F3H];   // 30 KB filter weights
    __shared__ float s_Fb[F3H];
    __shared__ float s_rbf[EPB][E_RBF];
    __shared__ float s_unit[EPB][3];
    __shared__ float s_fcut[EPB];
    __shared__ int   s_sd[EPB][2];        // [dst, src]

    for (int t = j; t < E_RBF * F3H; t += H) s_Fw[t] = Fw[t];
    for (int t = j; t < F3H; t += H)         s_Fb[t] = Fb[t];

    for (int t = j; t < EPB * E_RBF; t += H) {
        int ee = t / E_RBF, k = t % E_RBF;
        float dist = edist[e0 + ee];
        s_rbf[ee][k] = sinf(dist * (float)(k + 1) * (PI_F / CUTOFF_F)) / dist;
    }
    if (j < EPB) {
        int e = e0 + j;
        float dist = edist[e];
        s_fcut[j] = (dist < CUTOFF_F) ? 0.5f * (cosf(PI_F * dist / CUTOFF_F) + 1.0f) : 0.0f;
        float inv = 1.0f / dist;
        s_unit[j][0] = ediff[3 * e + 0] * inv;
        s_unit[j][1] = ediff[3 * e + 1] * inv;
        s_unit[j][2] = ediff[3 * e + 2] * inv;
        s_sd[j][0] = edge[2 * e];       // dst
        s_sd[j][1] = edge[2 * e + 1];   // src
    }
    __syncthreads();

    for (int ee = 0; ee < EPB; ee++) {
        int dst = s_sd[ee][0], src = s_sd[ee][1];
        float fcut = s_fcut[ee];
        float fw0 = s_Fb[j], fw1 = s_Fb[H + j], fw2 = s_Fb[2 * H + j];
#pragma unroll
        for (int k = 0; k < E_RBF; k++) {
            float r = s_rbf[ee][k];
            fw0 += r * s_Fw[k * F3H + j];
            fw1 += r * s_Fw[k * F3H + H + j];
            fw2 += r * s_Fw[k * F3H + 2 * H + j];
        }
        const float* so = g_so + (size_t)src * F3H;
        float gsv = fw0 * fcut * so[j];             // gate_sv
        float gev = fw1 * fcut * so[H + j];         // gate_ev
        float ms  = fw2 * fcut * so[2 * H + j];     // msg_s

        atomicAdd(&g_ns[dst * H + j], ms);

        const float* vin = g_vecA + (size_t)src * 3 * H;
        float* vout = g_vecB + (size_t)dst * 3 * H;
#pragma unroll
        for (int d = 0; d < 3; d++) {
            float mv = vin[d * H + j] * gsv + gev * s_unit[ee][d];
            atomicAdd(&vout[d * H + j], mv);
        }
    }
}

// ---------- update block: Uv/Vv, gated residual update (reads vecB, writes vecA + ns) ----------
__global__ void __launch_bounds__(H) k_update(const float* __restrict__ Uw,
                                              const float* __restrict__ Ub,
                                              const float* __restrict__ Vw,
                                              const float* __restrict__ Vb,
                                              const float* __restrict__ W1,
                                              const float* __restrict__ b1,
                                              const float* __restrict__ W2,
                                              const float* __restrict__ b2) {
    int i0 = blockIdx.x * NPB, j = threadIdx.x;
    __shared__ float s_v[NPB][3 * H];
    __shared__ float s_in[NPB][2 * H];
    __shared__ float s_h[NPB][H];

    float ns[NPB];
#pragma unroll
    for (int n = 0; n < NPB; n++) {
#pragma unroll
        for (int d = 0; d < 3; d++)
            s_v[n][d * H + j] = g_vecB[(i0 + n) * 3 * H + d * H + j];
        ns[n] = g_ns[(i0 + n) * H + j];
        s_in[n][H + j] = ns[n];
    }
    __syncthreads();

    float Uv[NPB][3], Vv[NPB][3];
    float ub = Ub[j], vb = Vb[j];
#pragma unroll
    for (int n = 0; n < NPB; n++)
#pragma unroll
        for (int d = 0; d < 3; d++) { Uv[n][d] = ub; Vv[n][d] = vb; }

    for (int k = 0; k < H; k++) {
        float u = Uw[k * H + j];
        float v = Vw[k * H + j];
#pragma unroll
        for (int n = 0; n < NPB; n++)
#pragma unroll
            for (int d = 0; d < 3; d++) {
                float x = s_v[n][d * H + k];
                Uv[n][d] += x * u;
                Vv[n][d] += x * v;
            }
    }
#pragma unroll
    for (int n = 0; n < NPB; n++)
        s_in[n][j] = sqrtf(Vv[n][0] * Vv[n][0] + Vv[n][1] * Vv[n][1] + Vv[n][2] * Vv[n][2]);
    __syncthreads();

    float acc[NPB];
    float bb = b1[j];
#pragma unroll
    for (int n = 0; n < NPB; n++) acc[n] = bb;
    for (int k = 0; k < 2 * H; k++) {
        float w = W1[k * H + j];
#pragma unroll
        for (int n = 0; n < NPB; n++) acc[n] += s_in[n][k] * w;
    }
#pragma unroll
    for (int n = 0; n < NPB; n++) s_h[n][j] = silu_f(acc[n]);
    __syncthreads();

    float a0[NPB], a1[NPB], a2[NPB];
    float c0 = b2[j], c1 = b2[H + j], c2 = b2[2 * H + j];
#pragma unroll
    for (int n = 0; n < NPB; n++) { a0[n] = c0; a1[n] = c1; a2[n] = c2; }
    for (int k = 0; k < H; k++) {
        float w0 = W2[k * F3H + j];
        float w1 = W2[k * F3H + H + j];
        float w2 = W2[k * F3H + 2 * H + j];
#pragma unroll
        for (int n = 0; n < NPB; n++) {
            float h = s_h[n][k];
            a0[n] += h * w0; a1[n] += h * w1; a2[n] += h * w2;
        }
    }
#pragma unroll
    for (int n = 0; n < NPB; n++) {
        float dot = 0.0f;
#pragma unroll
        for (int d = 0; d < 3; d++) {
            g_vecA[(i0 + n) * 3 * H + d * H + j] = s_v[n][d * H + j] + a0[n] * Uv[n][d];
            dot += Uv[n][d] * Vv[n][d];
        }
        g_ns[(i0 + n) * H + j] = ns[n] + a1[n] * dot + a2[n];
    }
}

// ---------- readout: out = silu(ns @ ro_w1 + b1) @ ro_w2 + b2 ----------
__global__ void __launch_bounds__(H) k_readout(const float* __restrict__ W1,
                                               const float* __restrict__ b1,
                                               const float* __restrict__ W2,
                                               const float* __restrict__ b2,
                                               float* __restrict__ out) {
    int i0 = blockIdx.x * NPB, j = threadIdx.x;
    __shared__ float s_x[NPB][H];
    __shared__ float s_h[NPB][H];
#pragma unroll
    for (int n = 0; n < NPB; n++) s_x[n][j] = g_ns[(i0 + n) * H + j];
    __syncthreads();

    float acc[NPB];
    float bb = b1[j];
#pragma unroll
    for (int n = 0; n < NPB; n++) acc[n] = bb;
    for (int k = 0; k < H; k++) {
        float w = W1[k * H + j];
#pragma unroll
        for (int n = 0; n < NPB; n++) acc[n] += s_x[n][k] * w;
    }
#pragma unroll
    for (int n = 0; n < NPB; n++) s_h[n][j] = silu_f(acc[n]);
    __syncthreads();

    float a[NPB];
    float c = b2[j];
#pragma unroll
    for (int n = 0; n < NPB; n++) a[n] = c;
    for (int k = 0; k < H; k++) {
        float w = W2[k * H + j];
#pragma unroll
        for (int n = 0; n < NPB; n++) a[n] += s_h[n][k] * w;
    }
#pragma unroll
    for (int n = 0; n < NPB; n++) out[(i0 + n) * H + j] = a[n];
}

// ---------- host launcher ----------
extern "C" void kernel_launch(void* const* d_in, const int* in_sizes, int n_in,
                              void* d_out, int out_size) {
    const int*   z      = (const int*)  d_in[0];
    const int*   edge   = (const int*)  d_in[1];
    const float* ediff  = (const float*)d_in[2];
    const float* edist  = (const float*)d_in[3];
    const float* embed  = (const float*)d_in[4];
    const float* mfw    = (const float*)d_in[5];   // (L, E, 3H)
    const float* mfb    = (const float*)d_in[6];   // (L, 3H)
    const float* mw1    = (const float*)d_in[7];   // (L, H, H)
    const float* mb1    = (const float*)d_in[8];   // (L, H)
    const float* mw2    = (const float*)d_in[9];   // (L, H, 3H)
    const float* mb2    = (const float*)d_in[10];  // (L, 3H)
    const float* uUw    = (const float*)d_in[11];  // (L, H, H)
    const float* uUb    = (const float*)d_in[12];
    const float* uVw    = (const float*)d_in[13];
    const float* uVb    = (const float*)d_in[14];
    const float* uw1    = (const float*)d_in[15];  // (L, 2H, H)
    const float* ub1    = (const float*)d_in[16];
    const float* uw2    = (const float*)d_in[17];  // (L, H, 3H)
    const float* ub2    = (const float*)d_in[18];
    const float* row1   = (const float*)d_in[19];  // (H, H)
    const float* rob1   = (const float*)d_in[20];
    const float* row2   = (const float*)d_in[21];  // (H, H)
    const float* rob2   = (const float*)d_in[22];
    float* out = (float*)d_out;

    k_init<<<N_NODES, H>>>(z, embed);

    int copy_threads = N_NODES * 3 * H / 4;
    for (int l = 0; l < L_LAYERS; l++) {
        k_scalar_out<<<N_NODES / NPB, H>>>(mw1 + l * H * H, mb1 + l * H,
                                           mw2 + l * H * F3H, mb2 + l * F3H);
        k_copy_vec<<<(copy_threads + 255) / 256, 256>>>();
        k_edge<<<N_EDGES / EPB, H>>>(edge, ediff, edist,
                                     mfw + l * E_RBF * F3H, mfb + l * F3H);
        k_update<<<N_NODES / NPB, H>>>(uUw + l * H * H, uUb + l * H,
                                       uVw + l * H * H, uVb + l * H,
                                       uw1 + l * 2 * H * H, ub1 + l * H,
                                       uw2 + l * H * F3H, ub2 + l * F3H);
    }
    k_readout<<<N_NODES / NPB, H>>>(row1, rob1, row2, rob2, out);
}